// round 1
// baseline (speedup 1.0000x reference)
#include <cuda_runtime.h>
#include <math_constants.h>
#include <math.h>

#define HID   4096
#define NH    32
#define HD    128
#define BSZ   2
#define SEQ   2048
#define TOK   (BSZ*SEQ)      /* 4096 */
#define QKV_N (3*HID)        /* 12288 */

// ---------------- device scratch (static, allocation-free) ----------------
__device__ int   g_idx[2*TOK];                       // [0,4096): vision slots, [4096,8192): language slots, -1 = empty
__device__ float g_q[(size_t)BSZ*NH*SEQ*HD];         // [B,NH,L,HD]
__device__ float g_k[(size_t)BSZ*NH*SEQ*HD];
__device__ float g_v[(size_t)BSZ*NH*SEQ*HD];
__device__ float g_ctx[(size_t)TOK*HID];             // [B,L,H] head-major within H

// ---------------- kernel 1: routing ----------------
__global__ void route_kernel(const int* __restrict__ tt) {
    __shared__ int cnt[2];
    int tid = threadIdx.x;
    if (tid < 2) cnt[tid] = 0;
    for (int i = tid; i < 2*TOK; i += blockDim.x) g_idx[i] = -1;
    __syncthreads();
    for (int t = tid; t < TOK; t += blockDim.x) {
        int l = t & (SEQ-1);
        int vm = (l < SEQ-1) && (tt[t] == 1) && (tt[t+1] == 1);
        int p = atomicAdd(&cnt[vm ? 0 : 1], 1);
        g_idx[(vm ? 0 : TOK) + p] = t;
    }
}

// ---------------- kernel 2: routed QKV GEMM ----------------
// C[slot, o] = sum_h X[tok(slot), h] * W[o, h]; grid (QKV_N/128, 2*TOK/128)
__global__ __launch_bounds__(256) void qkv_gemm(const float* __restrict__ X,
                                                const float* __restrict__ Wv,
                                                const float* __restrict__ Wl) {
    __shared__ __align__(16) float As[8][132];
    __shared__ __align__(16) float Bs[8][132];
    __shared__ int stok[128];
    const int tid = threadIdx.x;
    const int rt  = blockIdx.y;                 // 0..63, <32 => vision
    const float* __restrict__ W = (rt < (TOK/128)) ? Wv : Wl;

    int myv = 0;
    if (tid < 128) {
        int t = g_idx[rt*128 + tid];
        stok[tid] = t;
        myv = (t >= 0);
    }
    if (!__syncthreads_or(myv)) return;

    const int obase = blockIdx.x * 128;
    const int lr = tid >> 1;                    // 0..127
    const int lc = (tid & 1) * 4;               // 0 or 4
    const int mytok = stok[lr];
    const float* __restrict__ xrow = X + (size_t)(mytok < 0 ? 0 : mytok) * HID;
    const float* __restrict__ wrow = W + (size_t)(obase + lr) * HID;
    const int ty = tid >> 4, tx = tid & 15;

    float acc[8][8];
    #pragma unroll
    for (int i = 0; i < 8; i++)
        #pragma unroll
        for (int j = 0; j < 8; j++) acc[i][j] = 0.f;

    float4 av = make_float4(0,0,0,0);
    if (mytok >= 0) av = *(const float4*)(xrow + lc);
    float4 bv = *(const float4*)(wrow + lc);

    for (int k0 = 0; k0 < HID; k0 += 8) {
        As[lc+0][lr]=av.x; As[lc+1][lr]=av.y; As[lc+2][lr]=av.z; As[lc+3][lr]=av.w;
        Bs[lc+0][lr]=bv.x; Bs[lc+1][lr]=bv.y; Bs[lc+2][lr]=bv.z; Bs[lc+3][lr]=bv.w;
        __syncthreads();
        int kn = k0 + 8;
        if (kn < HID) {
            av = make_float4(0,0,0,0);
            if (mytok >= 0) av = *(const float4*)(xrow + kn + lc);
            bv = *(const float4*)(wrow + kn + lc);
        }
        #pragma unroll
        for (int kk = 0; kk < 8; kk++) {
            float4 a0 = *(const float4*)&As[kk][ty*8];
            float4 a1 = *(const float4*)&As[kk][ty*8+4];
            float4 b0 = *(const float4*)&Bs[kk][tx*8];
            float4 b1 = *(const float4*)&Bs[kk][tx*8+4];
            float ra[8] = {a0.x,a0.y,a0.z,a0.w,a1.x,a1.y,a1.z,a1.w};
            float rb[8] = {b0.x,b0.y,b0.z,b0.w,b1.x,b1.y,b1.z,b1.w};
            #pragma unroll
            for (int i = 0; i < 8; i++)
                #pragma unroll
                for (int j = 0; j < 8; j++) acc[i][j] = fmaf(ra[i], rb[j], acc[i][j]);
        }
        __syncthreads();
    }

    // epilogue: scatter into q/k/v [B,NH,L,HD] (each 128-wide N tile = one head of one part)
    const int part = blockIdx.x >> 5;           // 0=q,1=k,2=v
    const int head = blockIdx.x & 31;
    float* dst = (part == 0) ? g_q : (part == 1) ? g_k : g_v;
    #pragma unroll
    for (int i = 0; i < 8; i++) {
        int m = ty*8 + i;
        int t = stok[m];
        if (t < 0) continue;
        int b = t >> 11, l = t & (SEQ-1);
        float* drow = dst + (((size_t)(b*NH + head))*SEQ + l)*HD + tx*8;
        *(float4*)(drow)   = make_float4(acc[i][0],acc[i][1],acc[i][2],acc[i][3]);
        *(float4*)(drow+4) = make_float4(acc[i][4],acc[i][5],acc[i][6],acc[i][7]);
    }
}

// ---------------- kernel 3: RoPE (in place on g_q, g_k) ----------------
__global__ void rope_kernel(const int* __restrict__ pos_ids) {
    int i = blockIdx.x * blockDim.x + threadIdx.x;     // [0, B*NH*SEQ*64)
    if (i >= BSZ*NH*SEQ*(HD/2)) return;
    int d = i & 63;
    int l = (i >> 6) & (SEQ-1);
    int h = (i >> 17) & (NH-1);
    int b = i >> 22;
    int pos = pos_ids[(b << 11) | l];
    float invf = powf(10000.f, -(float)d * (1.f/64.f));
    float ang = (float)pos * invf;
    float s, c;
    sincosf(ang, &s, &c);
    size_t base = (((size_t)(b*NH + h))*SEQ + l)*HD + d;
    float x1 = g_q[base], x2 = g_q[base+64];
    g_q[base]    = x1*c - x2*s;
    g_q[base+64] = x2*c + x1*s;
    x1 = g_k[base]; x2 = g_k[base+64];
    g_k[base]    = x1*c - x2*s;
    g_k[base+64] = x2*c + x1*s;
}

// ---------------- kernel 4: flash attention (fp32) ----------------
// grid (SEQ/64, B*NH); 256 threads; dynamic smem
__global__ __launch_bounds__(256) void attn_kernel() {
    extern __shared__ __align__(16) float sm[];
    float* Qs   = sm;                    // [64][129]
    float* Ks   = Qs + 64*129;           // [64][129]
    float* Vs   = Ks + 64*129;           // [64][132] (float4 rows)
    float* St   = Vs + 64*132;           // [64][65], stored [c][r] (transposed)
    float* mrow = St + 64*65;            // [64]
    float* lrow = mrow + 64;             // [64]
    float* srow = lrow + 64;             // [64]
    float* red  = srow + 64;             // [4][64]

    const int tid = threadIdx.x;
    const int bh  = blockIdx.y;
    const int q0  = blockIdx.x * 64;
    const size_t base = (size_t)bh * SEQ * HD;
    const float* __restrict__ Qg = g_q + base;
    const float* __restrict__ Kg = g_k + base;
    const float* __restrict__ Vg = g_v + base;
    const int w = tid >> 5, lane = tid & 31;
    const float qscale = 0.08838834764831845f;   // 1/sqrt(128)

    for (int r = w; r < 64; r += 8) {
        float4 qv = *(const float4*)(Qg + (size_t)(q0+r)*HD + lane*4);
        Qs[r*129 + lane*4+0] = qv.x*qscale;
        Qs[r*129 + lane*4+1] = qv.y*qscale;
        Qs[r*129 + lane*4+2] = qv.z*qscale;
        Qs[r*129 + lane*4+3] = qv.w*qscale;
    }
    if (tid < 64) { mrow[tid] = -CUDART_INF_F; lrow[tid] = 0.f; }

    const int ty = tid >> 4, tx = tid & 15;
    const int sr = tid & 63, seg = tid >> 6;
    float acc_o[4][8];
    #pragma unroll
    for (int i = 0; i < 4; i++)
        #pragma unroll
        for (int j = 0; j < 8; j++) acc_o[i][j] = 0.f;
    __syncthreads();

    for (int kt = 0; kt < SEQ/64; kt++) {
        const int k0 = kt * 64;
        for (int r = w; r < 64; r += 8) {
            float4 kv = *(const float4*)(Kg + (size_t)(k0+r)*HD + lane*4);
            Ks[r*129 + lane*4+0] = kv.x;
            Ks[r*129 + lane*4+1] = kv.y;
            Ks[r*129 + lane*4+2] = kv.z;
            Ks[r*129 + lane*4+3] = kv.w;
            float4 vv = *(const float4*)(Vg + (size_t)(k0+r)*HD + lane*4);
            *(float4*)&Vs[r*132 + lane*4] = vv;
        }
        __syncthreads();

        // S = Qscaled @ K^T, 4x4 micro-tile, write transposed into St[c][r]
        float accs[4][4];
        #pragma unroll
        for (int i = 0; i < 4; i++)
            #pragma unroll
            for (int j = 0; j < 4; j++) accs[i][j] = 0.f;
        #pragma unroll 4
        for (int d = 0; d < HD; d++) {
            float rq[4], rk[4];
            #pragma unroll
            for (int i = 0; i < 4; i++) rq[i] = Qs[(ty*4+i)*129 + d];
            #pragma unroll
            for (int j = 0; j < 4; j++) rk[j] = Ks[(tx*4+j)*129 + d];
            #pragma unroll
            for (int i = 0; i < 4; i++)
                #pragma unroll
                for (int j = 0; j < 4; j++) accs[i][j] = fmaf(rq[i], rk[j], accs[i][j]);
        }
        #pragma unroll
        for (int j = 0; j < 4; j++)
            #pragma unroll
            for (int i = 0; i < 4; i++)
                St[(tx*4+j)*65 + ty*4+i] = accs[i][j];
        __syncthreads();

        // row max (per row r=sr, 4 segments of 16 keys)
        float pm = -CUDART_INF_F;
        #pragma unroll
        for (int c = seg*16; c < seg*16+16; c++) pm = fmaxf(pm, St[c*65 + sr]);
        red[seg*64 + sr] = pm;
        __syncthreads();
        if (tid < 64) {
            float mo = mrow[tid];
            float mn = fmaxf(fmaxf(red[tid], red[64+tid]), fmaxf(red[128+tid], red[192+tid]));
            mn = fmaxf(mo, mn);
            mrow[tid] = mn;
            srow[tid] = expf(mo - mn);     // 0 on first tile (mo = -inf)
        }
        __syncthreads();

        // exp pass + partial sums, and rescale O accumulators
        float mr = mrow[sr];
        float ps = 0.f;
        #pragma unroll
        for (int c = seg*16; c < seg*16+16; c++) {
            float p = expf(St[c*65 + sr] - mr);
            St[c*65 + sr] = p;
            ps += p;
        }
        red[seg*64 + sr] = ps;
        #pragma unroll
        for (int i = 0; i < 4; i++) {
            float sc = srow[ty*4+i];
            #pragma unroll
            for (int j = 0; j < 8; j++) acc_o[i][j] *= sc;
        }
        __syncthreads();
        if (tid < 64)
            lrow[tid] = lrow[tid]*srow[tid] + red[tid]+red[64+tid]+red[128+tid]+red[192+tid];

        // O += P @ V  (P from St[c][r], V natural)
        #pragma unroll 2
        for (int c = 0; c < 64; c++) {
            float rp[4];
            #pragma unroll
            for (int i = 0; i < 4; i++) rp[i] = St[c*65 + ty*4+i];
            float4 v0 = *(const float4*)&Vs[c*132 + tx*8];
            float4 v1 = *(const float4*)&Vs[c*132 + tx*8 + 4];
            float rv[8] = {v0.x,v0.y,v0.z,v0.w,v1.x,v1.y,v1.z,v1.w};
            #pragma unroll
            for (int i = 0; i < 4; i++)
                #pragma unroll
                for (int j = 0; j < 8; j++) acc_o[i][j] = fmaf(rp[i], rv[j], acc_o[i][j]);
        }
        __syncthreads();
    }

    // finalize: divide by l, write ctx [B, L, H] (head-major)
    const int b = bh >> 5, h = bh & 31;
    #pragma unroll
    for (int i = 0; i < 4; i++) {
        int r = ty*4 + i;
        float inv = 1.f / lrow[r];
        float* drow = g_ctx + ((size_t)(b*SEQ) + q0 + r)*HID + h*HD + tx*8;
        *(float4*)(drow)   = make_float4(acc_o[i][0]*inv, acc_o[i][1]*inv, acc_o[i][2]*inv, acc_o[i][3]*inv);
        *(float4*)(drow+4) = make_float4(acc_o[i][4]*inv, acc_o[i][5]*inv, acc_o[i][6]*inv, acc_o[i][7]*inv);
    }
}

// ---------------- kernel 5: routed output dense ----------------
__global__ __launch_bounds__(256) void dense_gemm(const float* __restrict__ Wv,
                                                  const float* __restrict__ Wl,
                                                  float* __restrict__ out) {
    __shared__ __align__(16) float As[8][132];
    __shared__ __align__(16) float Bs[8][132];
    __shared__ int stok[128];
    const int tid = threadIdx.x;
    const int rt  = blockIdx.y;
    const float* __restrict__ W = (rt < (TOK/128)) ? Wv : Wl;

    int myv = 0;
    if (tid < 128) {
        int t = g_idx[rt*128 + tid];
        stok[tid] = t;
        myv = (t >= 0);
    }
    if (!__syncthreads_or(myv)) return;

    const int obase = blockIdx.x * 128;
    const int lr = tid >> 1;
    const int lc = (tid & 1) * 4;
    const int mytok = stok[lr];
    const float* __restrict__ xrow = g_ctx + (size_t)(mytok < 0 ? 0 : mytok) * HID;
    const float* __restrict__ wrow = W + (size_t)(obase + lr) * HID;
    const int ty = tid >> 4, tx = tid & 15;

    float acc[8][8];
    #pragma unroll
    for (int i = 0; i < 8; i++)
        #pragma unroll
        for (int j = 0; j < 8; j++) acc[i][j] = 0.f;

    float4 av = make_float4(0,0,0,0);
    if (mytok >= 0) av = *(const float4*)(xrow + lc);
    float4 bv = *(const float4*)(wrow + lc);

    for (int k0 = 0; k0 < HID; k0 += 8) {
        As[lc+0][lr]=av.x; As[lc+1][lr]=av.y; As[lc+2][lr]=av.z; As[lc+3][lr]=av.w;
        Bs[lc+0][lr]=bv.x; Bs[lc+1][lr]=bv.y; Bs[lc+2][lr]=bv.z; Bs[lc+3][lr]=bv.w;
        __syncthreads();
        int kn = k0 + 8;
        if (kn < HID) {
            av = make_float4(0,0,0,0);
            if (mytok >= 0) av = *(const float4*)(xrow + kn + lc);
            bv = *(const float4*)(wrow + kn + lc);
        }
        #pragma unroll
        for (int kk = 0; kk < 8; kk++) {
            float4 a0 = *(const float4*)&As[kk][ty*8];
            float4 a1 = *(const float4*)&As[kk][ty*8+4];
            float4 b0 = *(const float4*)&Bs[kk][tx*8];
            float4 b1 = *(const float4*)&Bs[kk][tx*8+4];
            float ra[8] = {a0.x,a0.y,a0.z,a0.w,a1.x,a1.y,a1.z,a1.w};
            float rb[8] = {b0.x,b0.y,b0.z,b0.w,b1.x,b1.y,b1.z,b1.w};
            #pragma unroll
            for (int i = 0; i < 8; i++)
                #pragma unroll
                for (int j = 0; j < 8; j++) acc[i][j] = fmaf(ra[i], rb[j], acc[i][j]);
        }
        __syncthreads();
    }

    #pragma unroll
    for (int i = 0; i < 8; i++) {
        int m = ty*8 + i;
        int t = stok[m];
        if (t < 0) continue;
        float* drow = out + (size_t)t*HID + obase + tx*8;
        *(float4*)(drow)   = make_float4(acc[i][0],acc[i][1],acc[i][2],acc[i][3]);
        *(float4*)(drow+4) = make_float4(acc[i][4],acc[i][5],acc[i][6],acc[i][7]);
    }
}

// ---------------- launch ----------------
extern "C" void kernel_launch(void* const* d_in, const int* in_sizes, int n_in,
                              void* d_out, int out_size) {
    const float* x   = (const float*)d_in[0];
    const int*   tt  = (const int*)d_in[1];
    const int*   pos = (const int*)d_in[2];
    /* d_in[3] attention_mask: all zeros, unused (matches reference math) */
    const float* wvq = (const float*)d_in[4];
    const float* wlq = (const float*)d_in[5];
    const float* wvd = (const float*)d_in[6];
    const float* wld = (const float*)d_in[7];
    float* out = (float*)d_out;

    route_kernel<<<1, 1024>>>(tt);
    qkv_gemm<<<dim3(QKV_N/128, 2*TOK/128), 256>>>(x, wvq, wlq);
    rope_kernel<<<(BSZ*NH*SEQ*(HD/2) + 255)/256, 256>>>(pos);

    const size_t attn_smem = (size_t)(64*129 + 64*129 + 64*132 + 64*65 + 3*64 + 4*64) * sizeof(float);
    cudaFuncSetAttribute(attn_kernel, cudaFuncAttributeMaxDynamicSharedMemorySize, (int)attn_smem);
    attn_kernel<<<dim3(SEQ/64, BSZ*NH), 256, attn_smem>>>();

    dense_gemm<<<dim3(HID/128, 2*TOK/128), 256>>>(wvd, wld, out);
}